// round 3
// baseline (speedup 1.0000x reference)
#include <cuda_runtime.h>
#include <cuda_bf16.h>
#include <cstdint>

// Problem constants
#define BATCH 4
#define SEQ   2048
#define DMODEL 1024
#define NHEAD 16
#define HDIM  64
#define MROWS (BATCH*SEQ)         // 8192

#define NEG_INF __int_as_float(0xff800000)

// ---------------- scratch (device globals; no allocation allowed) ----------
__device__ float g_qh[(size_t)BATCH*NHEAD*SEQ*HDIM];   // (b,h,s,hd)
__device__ float g_kh[(size_t)BATCH*NHEAD*SEQ*HDIM];
__device__ float g_vh[(size_t)BATCH*NHEAD*SEQ*HDIM];
__device__ float g_ob[(size_t)BATCH*SEQ*DMODEL];       // attention out, (b,s,d)
__device__ unsigned char g_mask[BATCH*SEQ];
__device__ int g_mode;

// ---------------- mask dtype detection + canonicalization ------------------
__global__ void detect_mask_kernel(const unsigned char* __restrict__ p) {
    __shared__ int s1, s3;
    if (threadIdx.x == 0) { s1 = 0; s3 = 0; }
    __syncthreads();
    int l1 = 0, l3 = 0;
    for (int i = threadIdx.x; i < BATCH*SEQ; i += blockDim.x) {
        unsigned char v = p[i];
        int m = i & 3;
        if (m == 1 && v) l1 = 1;
        if (m == 3 && v) l3 = 1;
    }
    if (l1) atomicOr(&s1, 1);
    if (l3) atomicOr(&s3, 1);
    __syncthreads();
    if (threadIdx.x == 0) g_mode = s1 ? 0 : (s3 ? 1 : 2);  // 0=u8, 1=f32, 2=i32
}

__global__ void convert_mask_kernel(const unsigned char* __restrict__ p) {
    int i = blockIdx.x * blockDim.x + threadIdx.x;
    if (i >= BATCH*SEQ) return;
    int mode = g_mode;
    unsigned char r;
    if (mode == 0)      r = (p[i] != 0);
    else if (mode == 1) r = (((const float*)p)[i] != 0.0f);
    else                r = (((const int*)p)[i] != 0);
    g_mask[i] = r;
}

// ---------------- mma / ldmatrix primitives ---------------------------------
__device__ __forceinline__ void mma16816(float* c, const uint32_t* a, const uint32_t* b) {
    asm volatile(
        "mma.sync.aligned.m16n8k16.row.col.f32.bf16.bf16.f32 "
        "{%0,%1,%2,%3}, {%4,%5,%6,%7}, {%8,%9}, {%0,%1,%2,%3};"
        : "+f"(c[0]), "+f"(c[1]), "+f"(c[2]), "+f"(c[3])
        : "r"(a[0]), "r"(a[1]), "r"(a[2]), "r"(a[3]), "r"(b[0]), "r"(b[1]));
}

__device__ __forceinline__ void ldm_x4(uint32_t* r, uint32_t addr) {
    asm volatile("ldmatrix.sync.aligned.m8n8.x4.shared.b16 {%0,%1,%2,%3}, [%4];"
                 : "=r"(r[0]), "=r"(r[1]), "=r"(r[2]), "=r"(r[3]) : "r"(addr));
}
__device__ __forceinline__ void ldm_x2(uint32_t* r, uint32_t addr) {
    asm volatile("ldmatrix.sync.aligned.m8n8.x2.shared.b16 {%0,%1}, [%2];"
                 : "=r"(r[0]), "=r"(r[1]) : "r"(addr));
}
__device__ __forceinline__ void ldm_x2t(uint32_t* r, uint32_t addr) {
    asm volatile("ldmatrix.sync.aligned.m8n8.x2.trans.shared.b16 {%0,%1}, [%2];"
                 : "=r"(r[0]), "=r"(r[1]) : "r"(addr));
}

// fp32 -> bf16 hi/lo split, 4 elems, store as 2x bfloat162
__device__ __forceinline__ void sts_hl4(__nv_bfloat16* H, __nv_bfloat16* L,
                                        int idx, float4 v) {
    float f[4] = {v.x, v.y, v.z, v.w};
    #pragma unroll
    for (int p = 0; p < 2; ++p) {
        __nv_bfloat16 h0 = __float2bfloat16(f[2*p]);
        __nv_bfloat16 h1 = __float2bfloat16(f[2*p+1]);
        __nv_bfloat16 l0 = __float2bfloat16(f[2*p]   - __bfloat162float(h0));
        __nv_bfloat16 l1 = __float2bfloat16(f[2*p+1] - __bfloat162float(h1));
        __nv_bfloat162 h2; h2.x = h0; h2.y = h1;
        __nv_bfloat162 l2; l2.x = l0; l2.y = l1;
        *(__nv_bfloat162*)(H + idx + 2*p) = h2;
        *(__nv_bfloat162*)(L + idx + 2*p) = l2;
    }
}

// ---------------- GEMM: C = A @ W^T + bias (bf16x3, double-buffered) --------
// A: [M,K] f32 row-major; W: [N,K] f32 row-major. BM=BN=128, BK=32.
// 256 threads = 8 warps (2x4), warp tile 64x32, m16n8k16 fragments.
// grid.z selects (W, bias, C) so QKV runs as one launch.
#define GST 40               // smem row stride (bf16): 32 data + 8 pad
#define GREG (128*GST)       // elems per region
#define GBUF (4*GREG)        // elems per buffer (Ah,Al,Bh,Bl)

template <bool SPLIT>
__global__ __launch_bounds__(256, 1) void gemm3_kernel(
    const float* __restrict__ A,
    const float* __restrict__ W0, const float* __restrict__ b0, float* __restrict__ C0,
    const float* __restrict__ W1, const float* __restrict__ b1, float* __restrict__ C1,
    const float* __restrict__ W2, const float* __restrict__ b2, float* __restrict__ C2) {
    const int K = DMODEL;
    int z = blockIdx.z;
    const float* W    = (z == 0) ? W0 : (z == 1) ? W1 : W2;
    const float* bias = (z == 0) ? b0 : (z == 1) ? b1 : b2;
    float* C          = (z == 0) ? C0 : (z == 1) ? C1 : C2;

    extern __shared__ __align__(16) unsigned char smraw[];
    __nv_bfloat16* SM = (__nv_bfloat16*)smraw;

    int t = threadIdx.x;
    int lane = t & 31, warp = t >> 5;
    int wm = warp >> 2, wn = warp & 3;
    int m0 = blockIdx.y * 128, n0 = blockIdx.x * 128;

    int lrow = t >> 1;
    int lcol = (t & 1) * 16;
    const float4* Ag = (const float4*)(A + (size_t)(m0 + lrow) * K + lcol);
    const float4* Wg = (const float4*)(W + (size_t)(n0 + lrow) * K + lcol);

    uint32_t sb  = (uint32_t)__cvta_generic_to_shared(smraw);
    uint32_t aoff = ((lane & 15) * GST + ((lane >> 4) << 3)) * 2;
    uint32_t boff = ((lane & 7) * GST + (((lane >> 3) & 1) << 3)) * 2;
    int sidx = lrow * GST + lcol;

    float c[4][4][4] = {};
    float4 ra[4], rb[4];
    const int NIT = K / 32;   // 32

    // preload + store tile 0 into buf 0
    #pragma unroll
    for (int j = 0; j < 4; ++j) { ra[j] = Ag[j]; rb[j] = Wg[j]; }
    {
        __nv_bfloat16* Ah = SM;
        __nv_bfloat16* Al = SM + GREG;
        __nv_bfloat16* Bh = SM + 2*GREG;
        __nv_bfloat16* Bl = SM + 3*GREG;
        #pragma unroll
        for (int j = 0; j < 4; ++j) {
            sts_hl4(Ah, Al, sidx + j*4, ra[j]);
            sts_hl4(Bh, Bl, sidx + j*4, rb[j]);
        }
    }
    __syncthreads();
    // prefetch tile 1
    #pragma unroll
    for (int j = 0; j < 4; ++j) { ra[j] = Ag[8 + j]; rb[j] = Wg[8 + j]; }

    for (int it = 0; it < NIT; ++it) {
        // store tile it+1 into the other buffer (safe: sync at end of it-1)
        if (it + 1 < NIT) {
            int nb = (it + 1) & 1;
            __nv_bfloat16* Ah = SM + nb*GBUF;
            __nv_bfloat16* Al = Ah + GREG;
            __nv_bfloat16* Bh = Ah + 2*GREG;
            __nv_bfloat16* Bl = Ah + 3*GREG;
            #pragma unroll
            for (int j = 0; j < 4; ++j) {
                sts_hl4(Ah, Al, sidx + j*4, ra[j]);
                sts_hl4(Bh, Bl, sidx + j*4, rb[j]);
            }
        }
        // prefetch tile it+2
        if (it + 2 < NIT) {
            const float4* An = Ag + (it + 2) * 8;
            const float4* Wn = Wg + (it + 2) * 8;
            #pragma unroll
            for (int j = 0; j < 4; ++j) { ra[j] = An[j]; rb[j] = Wn[j]; }
        }
        // MMA on buffer it&1
        uint32_t bufB = sb + (uint32_t)((it & 1) * GBUF) * 2;
        const uint32_t AhB = bufB;
        const uint32_t AlB = bufB + GREG*2;
        const uint32_t BhB = bufB + 2*GREG*2;
        const uint32_t BlB = bufB + 3*GREG*2;
        #pragma unroll
        for (int ks = 0; ks < 2; ++ks) {
            uint32_t kbyte = (uint32_t)(ks * 16) * 2;
            uint32_t afh[4][4], afl[4][4];
            #pragma unroll
            for (int mi = 0; mi < 4; ++mi) {
                uint32_t base = (uint32_t)((wm*64 + mi*16) * GST) * 2 + kbyte + aoff;
                ldm_x4(afh[mi], AhB + base);
                ldm_x4(afl[mi], AlB + base);
            }
            uint32_t bfh[4][2], bfl[4][2];
            #pragma unroll
            for (int ni = 0; ni < 4; ++ni) {
                uint32_t base = (uint32_t)((wn*32 + ni*8) * GST) * 2 + kbyte + boff;
                ldm_x2(bfh[ni], BhB + base);
                ldm_x2(bfl[ni], BlB + base);
            }
            #pragma unroll
            for (int mi = 0; mi < 4; ++mi)
                #pragma unroll
                for (int ni = 0; ni < 4; ++ni) {
                    mma16816(c[mi][ni], afh[mi], bfh[ni]);
                    mma16816(c[mi][ni], afh[mi], bfl[ni]);
                    mma16816(c[mi][ni], afl[mi], bfh[ni]);
                }
        }
        __syncthreads();
    }

    // epilogue
    int g = lane >> 2, cq = (lane & 3) * 2;
    #pragma unroll
    for (int mi = 0; mi < 4; ++mi) {
        int r0 = m0 + wm*64 + mi*16 + g;
        int r1 = r0 + 8;
        #pragma unroll
        for (int ni = 0; ni < 4; ++ni) {
            int col = n0 + wn*32 + ni*8 + cq;
            float b0v = bias[col], b1v = bias[col + 1];
            float2 v0 = {c[mi][ni][0] + b0v, c[mi][ni][1] + b1v};
            float2 v1 = {c[mi][ni][2] + b0v, c[mi][ni][3] + b1v};
            if (SPLIT) {
                int hh = col >> 6, hd = col & 63;
                int bi0 = r0 >> 11, s0 = r0 & 2047;
                int bi1 = r1 >> 11, s1 = r1 & 2047;
                *(float2*)&C[((((size_t)bi0*NHEAD + hh)*SEQ) + s0)*HDIM + hd] = v0;
                *(float2*)&C[((((size_t)bi1*NHEAD + hh)*SEQ) + s1)*HDIM + hd] = v1;
            } else {
                *(float2*)&C[(size_t)r0*DMODEL + col] = v0;
                *(float2*)&C[(size_t)r1*DMODEL + col] = v1;
            }
        }
    }
}

// ---------------- Flash attention (bf16x3, double-buffered K/V) -------------
// grid (SEQ/64, B*H), 128 threads (4 warps). Warp w owns query rows [w*16,+16).
#define AST 72               // smem row stride (bf16): 64 data + 8 pad
#define ATILE (64*AST)       // elems per region

__global__ __launch_bounds__(128, 1) void attn_mma_kernel(const float* __restrict__ qh,
                                                          const float* __restrict__ kh,
                                                          const float* __restrict__ vh,
                                                          float* __restrict__ ob) {
    extern __shared__ __align__(16) unsigned char smraw[];
    __nv_bfloat16* SM = (__nv_bfloat16*)smraw;
    // layout: buf0 {Kh,Kl,Vh,Vl}, buf1 {Kh,Kl,Vh,Vl}, Ph, Pl, km[2][64]
    __nv_bfloat16* Psh = SM + 8*ATILE;
    __nv_bfloat16* Psl = SM + 9*ATILE;
    float* km = (float*)(SM + 10*ATILE);

    int t = threadIdx.x, lane = t & 31, w = t >> 5;
    int g = lane >> 2, cq = (lane & 3) * 2;
    int qt = blockIdx.x, bh = blockIdx.y;
    int b = bh >> 4, h = bh & 15;
    int q0 = qt * 64;
    const float* qb = qh + ((size_t)bh * SEQ + q0) * HDIM;
    const float* kb = kh + (size_t)bh * SEQ * HDIM;
    const float* vb = vh + (size_t)bh * SEQ * HDIM;
    const unsigned char* mb = g_mask + b * SEQ;

    uint32_t sbse = (uint32_t)__cvta_generic_to_shared(smraw);
    const uint32_t PshB = sbse + 8*ATILE*2;
    const uint32_t PslB = sbse + 9*ATILE*2;
    uint32_t aoff = ((lane & 15) * AST + ((lane >> 4) << 3)) * 2;
    uint32_t boff = ((lane & 7) * AST + (((lane >> 3) & 1) << 3)) * 2;
    uint32_t voff = ((lane & 15) * AST) * 2;

    int lrow = t >> 1, lcol0 = (t & 1) * 32;
    int sidx = lrow * AST + lcol0;

    // stage Q (fp32 -> bf16 hi/lo in P region) and load persistent Q fragments
    {
        const float4* Qg = (const float4*)(qb + lrow*HDIM + lcol0);
        #pragma unroll
        for (int j = 0; j < 8; ++j) sts_hl4(Psh, Psl, sidx + j*4, Qg[j]);
    }
    __syncthreads();
    uint32_t qfh[4][4], qfl[4][4];
    #pragma unroll
    for (int kt = 0; kt < 4; ++kt) {
        uint32_t base = (uint32_t)(w*16*AST + kt*16)*2 + aoff;
        ldm_x4(qfh[kt], PshB + base);
        ldm_x4(qfl[kt], PslB + base);
    }

    const int NT = SEQ / 64;   // 32
    float4 rk[8], rv[8];
    // preload + store tile 0 into kv buf 0
    {
        const float4* Kg = (const float4*)(kb + (size_t)lrow*HDIM + lcol0);
        const float4* Vg = (const float4*)(vb + (size_t)lrow*HDIM + lcol0);
        #pragma unroll
        for (int j = 0; j < 8; ++j) { rk[j] = Kg[j]; rv[j] = Vg[j]; }
        __nv_bfloat16* Ksh = SM;
        __nv_bfloat16* Ksl = SM + ATILE;
        __nv_bfloat16* Vsh = SM + 2*ATILE;
        __nv_bfloat16* Vsl = SM + 3*ATILE;
        #pragma unroll
        for (int j = 0; j < 8; ++j) {
            sts_hl4(Ksh, Ksl, sidx + j*4, rk[j]);
            sts_hl4(Vsh, Vsl, sidx + j*4, rv[j]);
        }
        if (t < 64) km[t] = mb[t] ? 0.0f : NEG_INF;
    }
    __syncthreads();
    // prefetch tile 1
    {
        const float4* Kg = (const float4*)(kb + (size_t)(64 + lrow)*HDIM + lcol0);
        const float4* Vg = (const float4*)(vb + (size_t)(64 + lrow)*HDIM + lcol0);
        #pragma unroll
        for (int j = 0; j < 8; ++j) { rk[j] = Kg[j]; rv[j] = Vg[j]; }
    }

    float oc[8][4] = {};
    float m0r = NEG_INF, m1r = NEG_INF, l0r = 0.f, l1r = 0.f;

    for (int it = 0; it < NT; ++it) {
        // store tile it+1 into other buffer
        if (it + 1 < NT) {
            int nb = (it + 1) & 1;
            __nv_bfloat16* Ksh = SM + nb*4*ATILE;
            __nv_bfloat16* Ksl = Ksh + ATILE;
            __nv_bfloat16* Vsh = Ksh + 2*ATILE;
            __nv_bfloat16* Vsl = Ksh + 3*ATILE;
            #pragma unroll
            for (int j = 0; j < 8; ++j) {
                sts_hl4(Ksh, Ksl, sidx + j*4, rk[j]);
                sts_hl4(Vsh, Vsl, sidx + j*4, rv[j]);
            }
            if (t < 64) km[nb*64 + t] = mb[(it+1)*64 + t] ? 0.0f : NEG_INF;
        }
        // prefetch tile it+2
        if (it + 2 < NT) {
            const float4* Kg = (const float4*)(kb + (size_t)((it+2)*64 + lrow)*HDIM + lcol0);
            const float4* Vg = (const float4*)(vb + (size_t)((it+2)*64 + lrow)*HDIM + lcol0);
            #pragma unroll
            for (int j = 0; j < 8; ++j) { rk[j] = Kg[j]; rv[j] = Vg[j]; }
        }

        int cb = it & 1;
        uint32_t kvB = sbse + (uint32_t)(cb*4*ATILE)*2;
        const uint32_t KshB = kvB;
        const uint32_t KslB = kvB + ATILE*2;
        const uint32_t VshB = kvB + 2*ATILE*2;
        const uint32_t VslB = kvB + 3*ATILE*2;
        const float* kmc = km + cb*64;

        // S = Q K^T  (16 rows x 64 keys per warp)
        float sc[8][4] = {};
        #pragma unroll
        for (int nt = 0; nt < 8; ++nt) {
            #pragma unroll
            for (int kt = 0; kt < 4; ++kt) {
                uint32_t base = (uint32_t)(nt*8*AST + kt*16)*2 + boff;
                uint32_t b2h[2], b2l[2];
                ldm_x2(b2h, KshB + base);
                ldm_x2(b2l, KslB + base);
                mma16816(sc[nt], qfh[kt], b2h);
                mma16816(sc[nt], qfh[kt], b2l);
                mma16816(sc[nt], qfl[kt], b2h);
            }
        }

        // online softmax (rows g and g+8 of warp strip)
        float r0m = NEG_INF, r1m = NEG_INF;
        #pragma unroll
        for (int nt = 0; nt < 8; ++nt) {
            float a0 = kmc[nt*8 + cq], a1 = kmc[nt*8 + cq + 1];
            sc[nt][0] = sc[nt][0]*0.125f + a0;
            sc[nt][1] = sc[nt][1]*0.125f + a1;
            sc[nt][2] = sc[nt][2]*0.125f + a0;
            sc[nt][3] = sc[nt][3]*0.125f + a1;
            r0m = fmaxf(r0m, fmaxf(sc[nt][0], sc[nt][1]));
            r1m = fmaxf(r1m, fmaxf(sc[nt][2], sc[nt][3]));
        }
        r0m = fmaxf(r0m, __shfl_xor_sync(0xffffffffu, r0m, 1));
        r0m = fmaxf(r0m, __shfl_xor_sync(0xffffffffu, r0m, 2));
        r1m = fmaxf(r1m, __shfl_xor_sync(0xffffffffu, r1m, 1));
        r1m = fmaxf(r1m, __shfl_xor_sync(0xffffffffu, r1m, 2));
        float mn0 = fmaxf(m0r, r0m), mn1 = fmaxf(m1r, r1m);
        float ms0 = (mn0 == NEG_INF) ? 0.0f : mn0;
        float ms1 = (mn1 == NEG_INF) ? 0.0f : mn1;
        float al0 = __expf(m0r - ms0), al1 = __expf(m1r - ms1);  // -inf -> 0, no NaN
        m0r = mn0; m1r = mn1;

        float rs0 = 0.f, rs1 = 0.f;
        int pr0 = (w*16 + g) * AST, pr1 = (w*16 + g + 8) * AST;
        #pragma unroll
        for (int nt = 0; nt < 8; ++nt) {
            float p0 = __expf(sc[nt][0] - ms0), p1 = __expf(sc[nt][1] - ms0);
            float p2 = __expf(sc[nt][2] - ms1), p3 = __expf(sc[nt][3] - ms1);
            rs0 += p0 + p1; rs1 += p2 + p3;
            __nv_bfloat16 h0 = __float2bfloat16(p0), h1 = __float2bfloat16(p1);
            __nv_bfloat16 h2 = __float2bfloat16(p2), h3 = __float2bfloat16(p3);
            __nv_bfloat162 hv0; hv0.x = h0; hv0.y = h1;
            __nv_bfloat162 hv1; hv1.x = h2; hv1.y = h3;
            __nv_bfloat162 lv0, lv1;
            lv0.x = __float2bfloat16(p0 - __bfloat162float(h0));
            lv0.y = __float2bfloat16(p1 - __bfloat162float(h1));
            lv1.x = __float2bfloat16(p2 - __bfloat162float(h2));
            lv1.y = __float2bfloat16(p3 - __bfloat162float(h3));
            *(__nv_bfloat162*)(Psh + pr0 + nt*8 + cq) = hv0;
            *(__nv_bfloat162*)(Psh + pr1 + nt*8 + cq) = hv1;
            *(__nv_bfloat162*)(Psl + pr0 + nt*8 + cq) = lv0;
            *(__nv_bfloat162*)(Psl + pr1 + nt*8 + cq) = lv1;
        }
        rs0 += __shfl_xor_sync(0xffffffffu, rs0, 1);
        rs0 += __shfl_xor_sync(0xffffffffu, rs0, 2);
        rs1 += __shfl_xor_sync(0xffffffffu, rs1, 1);
        rs1 += __shfl_xor_sync(0xffffffffu, rs1, 2);
        l0r = l0r * al0 + rs0;
        l1r = l1r * al1 + rs1;
        #pragma unroll
        for (int nt = 0; nt < 8; ++nt) {
            oc[nt][0] *= al0; oc[nt][1] *= al0;
            oc[nt][2] *= al1; oc[nt][3] *= al1;
        }
        __syncwarp();   // P rows are warp-private

        // O += P V
        #pragma unroll
        for (int kt = 0; kt < 4; ++kt) {
            uint32_t pb = (uint32_t)(w*16*AST + kt*16)*2 + aoff;
            uint32_t pfh[4], pfl[4];
            ldm_x4(pfh, PshB + pb);
            ldm_x4(pfl, PslB + pb);
            #pragma unroll
            for (int nt = 0; nt < 8; ++nt) {
                uint32_t vb2 = (uint32_t)(kt*16*AST + nt*8)*2 + voff;
                uint32_t v2h[2], v2l[2];
                ldm_x2t(v2h, VshB + vb2);
                ldm_x2t(v2l, VslB + vb2);
                mma16816(oc[nt], pfh, v2h);
                mma16816(oc[nt], pfh, v2l);
                mma16816(oc[nt], pfl, v2h);
            }
        }
        __syncthreads();
    }

    // epilogue: normalize, zero masked query rows, write (b,s,d)
    int r0 = w*16 + g, r1 = r0 + 8;
    float inv0 = (mb[q0 + r0] && l0r > 0.f) ? 1.0f / l0r : 0.0f;
    float inv1 = (mb[q0 + r1] && l1r > 0.f) ? 1.0f / l1r : 0.0f;
    size_t base0 = ((size_t)b*SEQ + q0 + r0)*DMODEL + h*HDIM;
    size_t base1 = ((size_t)b*SEQ + q0 + r1)*DMODEL + h*HDIM;
    #pragma unroll
    for (int nt = 0; nt < 8; ++nt) {
        float2 v0 = {oc[nt][0]*inv0, oc[nt][1]*inv0};
        float2 v1 = {oc[nt][2]*inv1, oc[nt][3]*inv1};
        *(float2*)&ob[base0 + nt*8 + cq] = v0;
        *(float2*)&ob[base1 + nt*8 + cq] = v1;
    }
}

// ---------------- launch ----------------------------------------------------
extern "C" void kernel_launch(void* const* d_in, const int* in_sizes, int n_in,
                              void* d_out, int out_size) {
    const float* q    = (const float*)d_in[0];
    const unsigned char* mask = (const unsigned char*)d_in[1];
    const float* Wq   = (const float*)d_in[2];
    const float* bq   = (const float*)d_in[3];
    const float* Wk   = (const float*)d_in[4];
    const float* bk   = (const float*)d_in[5];
    const float* Wv   = (const float*)d_in[6];
    const float* bv   = (const float*)d_in[7];
    const float* Wo   = (const float*)d_in[8];
    const float* bo   = (const float*)d_in[9];
    float* out = (float*)d_out;

    float *qh, *kh, *vh, *obuf;
    cudaGetSymbolAddress((void**)&qh, g_qh);
    cudaGetSymbolAddress((void**)&kh, g_kh);
    cudaGetSymbolAddress((void**)&vh, g_vh);
    cudaGetSymbolAddress((void**)&obuf, g_ob);

    detect_mask_kernel<<<1, 256>>>(mask);
    convert_mask_kernel<<<(BATCH*SEQ + 255) / 256, 256>>>(mask);

    const int gemm_smem = 2 * GBUF * 2;                 // 81920 B
    const int attn_smem = 10 * ATILE * 2 + 2 * 64 * 4;  // 92672 B
    static bool attr_done = false;
    if (!attr_done) {
        cudaFuncSetAttribute(gemm3_kernel<true>,
                             cudaFuncAttributeMaxDynamicSharedMemorySize, gemm_smem);
        cudaFuncSetAttribute(gemm3_kernel<false>,
                             cudaFuncAttributeMaxDynamicSharedMemorySize, gemm_smem);
        cudaFuncSetAttribute(attn_mma_kernel,
                             cudaFuncAttributeMaxDynamicSharedMemorySize, attn_smem);
        attr_done = true;
    }

    dim3 gq(DMODEL / 128, MROWS / 128, 3);   // fused QKV
    gemm3_kernel<true><<<gq, 256, gemm_smem>>>(q, Wq, bq, qh, Wk, bk, kh, Wv, bv, vh);

    attn_mma_kernel<<<dim3(SEQ / 64, BATCH * NHEAD), 128, attn_smem>>>(qh, kh, vh, obuf);

    dim3 go(DMODEL / 128, MROWS / 128, 1);
    gemm3_kernel<false><<<go, 256, gemm_smem>>>(obuf, Wo, bo, out, Wo, bo, out, Wo, bo, out);
}

// round 5
// speedup vs baseline: 1.1453x; 1.1453x over previous
#include <cuda_runtime.h>
#include <cuda_bf16.h>
#include <cstdint>

// Problem constants
#define BATCH 4
#define SEQ   2048
#define DMODEL 1024
#define NHEAD 16
#define HDIM  64
#define MROWS (BATCH*SEQ)         // 8192

#define NEG_INF __int_as_float(0xff800000)

// ---------------- scratch (device globals; no allocation allowed) ----------
#define NELEM (8192*1024)
__device__ __nv_bfloat16 g_ah[NELEM],  g_al[NELEM];            // input q hi/lo
__device__ __nv_bfloat16 g_wh[4*1024*1024], g_wl[4*1024*1024]; // Wq,Wk,Wv,Wo hi/lo
__device__ __nv_bfloat16 g_qhh[NELEM], g_qhl[NELEM];           // Q heads (b,h,s,hd)
__device__ __nv_bfloat16 g_khh[NELEM], g_khl[NELEM];
__device__ __nv_bfloat16 g_vhh[NELEM], g_vhl[NELEM];
__device__ __nv_bfloat16 g_oh[NELEM],  g_ol[NELEM];            // attn out (b,s,d)
__device__ unsigned char g_mask[BATCH*SEQ];
__device__ int g_mode;

// ---------------- mask dtype detection + canonicalization ------------------
__global__ void detect_mask_kernel(const unsigned char* __restrict__ p) {
    __shared__ int s1, s3;
    if (threadIdx.x == 0) { s1 = 0; s3 = 0; }
    __syncthreads();
    int l1 = 0, l3 = 0;
    for (int i = threadIdx.x; i < BATCH*SEQ; i += blockDim.x) {
        unsigned char v = p[i];
        int m = i & 3;
        if (m == 1 && v) l1 = 1;
        if (m == 3 && v) l3 = 1;
    }
    if (l1) atomicOr(&s1, 1);
    if (l3) atomicOr(&s3, 1);
    __syncthreads();
    if (threadIdx.x == 0) g_mode = s1 ? 0 : (s3 ? 1 : 2);  // 0=u8, 1=f32, 2=i32
}

__global__ void convert_mask_kernel(const unsigned char* __restrict__ p) {
    int i = blockIdx.x * blockDim.x + threadIdx.x;
    if (i >= BATCH*SEQ) return;
    int mode = g_mode;
    unsigned char r;
    if (mode == 0)      r = (p[i] != 0);
    else if (mode == 1) r = (((const float*)p)[i] != 0.0f);
    else                r = (((const int*)p)[i] != 0);
    g_mask[i] = r;
}

// ---------------- fp32 -> bf16 hi/lo split kernels --------------------------
__device__ __forceinline__ void split4(float4 v, __nv_bfloat16* h, __nv_bfloat16* l) {
    float f[4] = {v.x, v.y, v.z, v.w};
    #pragma unroll
    for (int p = 0; p < 2; ++p) {
        __nv_bfloat162 hp, lp;
        hp.x = __float2bfloat16(f[2*p]);
        hp.y = __float2bfloat16(f[2*p+1]);
        lp.x = __float2bfloat16(f[2*p]   - __bfloat162float(hp.x));
        lp.y = __float2bfloat16(f[2*p+1] - __bfloat162float(hp.y));
        *(__nv_bfloat162*)(h + 2*p) = hp;
        *(__nv_bfloat162*)(l + 2*p) = lp;
    }
}

__global__ void split_kernel(const float* __restrict__ src,
                             __nv_bfloat16* __restrict__ hi,
                             __nv_bfloat16* __restrict__ lo, int n) {
    int i = (blockIdx.x * blockDim.x + threadIdx.x) * 4;
    if (i >= n) return;
    split4(*(const float4*)(src + i), hi + i, lo + i);
}

__global__ void split_w_kernel(const float* __restrict__ w0, const float* __restrict__ w1,
                               const float* __restrict__ w2, const float* __restrict__ w3,
                               __nv_bfloat16* __restrict__ hi, __nv_bfloat16* __restrict__ lo) {
    int z = blockIdx.z;
    const float* src = (z==0)?w0:(z==1)?w1:(z==2)?w2:w3;
    size_t off = (size_t)z * 1024 * 1024;
    int i = (blockIdx.x * blockDim.x + threadIdx.x) * 4;
    split4(*(const float4*)(src + i), hi + off + i, lo + off + i);
}

// ---------------- mma / ldmatrix / cp.async primitives ----------------------
__device__ __forceinline__ void mma16816(float* c, const uint32_t* a, const uint32_t* b) {
    asm volatile(
        "mma.sync.aligned.m16n8k16.row.col.f32.bf16.bf16.f32 "
        "{%0,%1,%2,%3}, {%4,%5,%6,%7}, {%8,%9}, {%0,%1,%2,%3};"
        : "+f"(c[0]), "+f"(c[1]), "+f"(c[2]), "+f"(c[3])
        : "r"(a[0]), "r"(a[1]), "r"(a[2]), "r"(a[3]), "r"(b[0]), "r"(b[1]));
}
__device__ __forceinline__ void ldm_x4(uint32_t* r, uint32_t addr) {
    asm volatile("ldmatrix.sync.aligned.m8n8.x4.shared.b16 {%0,%1,%2,%3}, [%4];"
                 : "=r"(r[0]), "=r"(r[1]), "=r"(r[2]), "=r"(r[3]) : "r"(addr));
}
__device__ __forceinline__ void ldm_x2(uint32_t* r, uint32_t addr) {
    asm volatile("ldmatrix.sync.aligned.m8n8.x2.shared.b16 {%0,%1}, [%2];"
                 : "=r"(r[0]), "=r"(r[1]) : "r"(addr));
}
__device__ __forceinline__ void ldm_x2t(uint32_t* r, uint32_t addr) {
    asm volatile("ldmatrix.sync.aligned.m8n8.x2.trans.shared.b16 {%0,%1}, [%2];"
                 : "=r"(r[0]), "=r"(r[1]) : "r"(addr));
}
#define CP16(dst, src) \
    asm volatile("cp.async.cg.shared.global [%0], [%1], 16;" :: "r"(dst), "l"(src))
#define CP_COMMIT() asm volatile("cp.async.commit_group;" ::: "memory")
#define CP_WAIT(n)  asm volatile("cp.async.wait_group %0;" :: "n"(n) : "memory")

// ---------------- GEMM: C = A @ W^T + bias (bf16x3, cp.async 3-stage) -------
// A hi/lo, W hi/lo: bf16 [.,1024] row-major. BM=BN=128, BK=32.
// smem stage: region A = 128 rows x 128B [hi 64B | lo 64B], region B same.
// SW128 swizzle: chunk bits [6:4] ^= row&7.  8 warps (2x4), warp tile 64x32.
#define GSTAGE 32768
#define NIT 32

template <bool SPLIT>
__global__ __launch_bounds__(256, 1) void gemm_cp_kernel(
    const __nv_bfloat16* __restrict__ Ahg, const __nv_bfloat16* __restrict__ Alg,
    const __nv_bfloat16* __restrict__ Whb, const __nv_bfloat16* __restrict__ Wlb, int woff,
    const float* b0, const float* b1, const float* b2,
    __nv_bfloat16* C0h, __nv_bfloat16* C0l,
    __nv_bfloat16* C1h, __nv_bfloat16* C1l,
    __nv_bfloat16* C2h, __nv_bfloat16* C2l,
    float* Cf)
{
    int z = blockIdx.z;
    const __nv_bfloat16* Wh = Whb + (size_t)(woff + z) * 1024 * 1024;
    const __nv_bfloat16* Wl = Wlb + (size_t)(woff + z) * 1024 * 1024;
    const float* bias = (z == 0) ? b0 : (z == 1) ? b1 : b2;
    __nv_bfloat16* Ch = (z == 0) ? C0h : (z == 1) ? C1h : C2h;
    __nv_bfloat16* Cl = (z == 0) ? C0l : (z == 1) ? C1l : C2l;

    extern __shared__ __align__(128) unsigned char smraw[];
    uint32_t sb = (uint32_t)__cvta_generic_to_shared(smraw);

    int t = threadIdx.x, lane = t & 31, warp = t >> 5;
    int wm = warp >> 2, wn = warp & 3;
    int m0 = blockIdx.y * 128, n0 = blockIdx.x * 128;

    int row = t >> 1, half = t & 1;
    const __nv_bfloat16* srcA = (half ? Alg : Ahg) + (size_t)(m0 + row) * 1024;
    const __nv_bfloat16* srcB = (half ? Wl : Wh)  + (size_t)(n0 + row) * 1024;
    uint32_t rxor = (uint32_t)((row & 7) << 4);
    uint32_t dA = sb + row * 128;

    auto issue = [&](int ch) {
        uint32_t base = dA + (uint32_t)(ch % 3) * GSTAGE;
        const __nv_bfloat16* sa = srcA + ch * 32;
        const __nv_bfloat16* sbp = srcB + ch * 32;
        #pragma unroll
        for (int j = 0; j < 4; ++j) {
            uint32_t c = (uint32_t)(half * 64 + j * 16) ^ rxor;
            CP16(base + c,         sa  + j * 8);
            CP16(base + 16384 + c, sbp + j * 8);
        }
    };

    float c[4][4][4] = {};
    uint32_t x = (uint32_t)((lane & 7) << 4);
    uint32_t arow = (uint32_t)(wm * 64 + (lane & 15));
    uint32_t acol = (uint32_t)((lane >> 4) << 4);
    uint32_t brow = (uint32_t)(wn * 32 + (lane & 7));
    uint32_t bcol = (uint32_t)(((lane >> 3) & 1) << 4);

    issue(0); CP_COMMIT();
    issue(1); CP_COMMIT();

    for (int it = 0; it < NIT; ++it) {
        if (it + 2 < NIT) { issue(it + 2); CP_COMMIT(); CP_WAIT(2); }
        else if (it + 1 < NIT) { CP_WAIT(1); }
        else { CP_WAIT(0); }
        __syncthreads();

        uint32_t Abase = sb + (uint32_t)(it % 3) * GSTAGE;
        uint32_t Bbase = Abase + 16384;
        #pragma unroll
        for (int ks = 0; ks < 2; ++ks) {
            uint32_t ch = (uint32_t)(ks * 32) + acol;
            uint32_t afh[4][4], afl[4][4];
            #pragma unroll
            for (int mi = 0; mi < 4; ++mi) {
                uint32_t ra = Abase + (arow + mi * 16) * 128;
                ldm_x4(afh[mi], ra + (ch ^ x));
                ldm_x4(afl[mi], ra + ((ch + 64) ^ x));
            }
            uint32_t cb = (uint32_t)(ks * 32) + bcol;
            uint32_t bfh[4][2], bfl[4][2];
            #pragma unroll
            for (int ni = 0; ni < 4; ++ni) {
                uint32_t rb = Bbase + (brow + ni * 8) * 128;
                ldm_x2(bfh[ni], rb + (cb ^ x));
                ldm_x2(bfl[ni], rb + ((cb + 64) ^ x));
            }
            #pragma unroll
            for (int mi = 0; mi < 4; ++mi)
                #pragma unroll
                for (int ni = 0; ni < 4; ++ni) {
                    mma16816(c[mi][ni], afh[mi], bfh[ni]);
                    mma16816(c[mi][ni], afh[mi], bfl[ni]);
                    mma16816(c[mi][ni], afl[mi], bfh[ni]);
                }
        }
        __syncthreads();
    }

    // epilogue
    int g = lane >> 2, cq = (lane & 3) * 2;
    #pragma unroll
    for (int mi = 0; mi < 4; ++mi) {
        int r0 = m0 + wm*64 + mi*16 + g;
        int r1 = r0 + 8;
        #pragma unroll
        for (int ni = 0; ni < 4; ++ni) {
            int col = n0 + wn*32 + ni*8 + cq;
            float b0v = __ldg(bias + col), b1v = __ldg(bias + col + 1);
            float v00 = c[mi][ni][0] + b0v, v01 = c[mi][ni][1] + b1v;
            float v10 = c[mi][ni][2] + b0v, v11 = c[mi][ni][3] + b1v;
            if (SPLIT) {
                int hh = col >> 6, hd = col & 63;
                int bi0 = r0 >> 11, s0 = r0 & 2047;
                int bi1 = r1 >> 11, s1 = r1 & 2047;
                size_t i0 = ((((size_t)bi0*NHEAD + hh)*SEQ) + s0)*HDIM + hd;
                size_t i1 = ((((size_t)bi1*NHEAD + hh)*SEQ) + s1)*HDIM + hd;
                __nv_bfloat162 h2, l2;
                h2.x = __float2bfloat16(v00); h2.y = __float2bfloat16(v01);
                l2.x = __float2bfloat16(v00 - __bfloat162float(h2.x));
                l2.y = __float2bfloat16(v01 - __bfloat162float(h2.y));
                *(__nv_bfloat162*)(Ch + i0) = h2;
                *(__nv_bfloat162*)(Cl + i0) = l2;
                h2.x = __float2bfloat16(v10); h2.y = __float2bfloat16(v11);
                l2.x = __float2bfloat16(v10 - __bfloat162float(h2.x));
                l2.y = __float2bfloat16(v11 - __bfloat162float(h2.y));
                *(__nv_bfloat162*)(Ch + i1) = h2;
                *(__nv_bfloat162*)(Cl + i1) = l2;
            } else {
                float2 v0 = {v00, v01}, v1 = {v10, v11};
                *(float2*)&Cf[(size_t)r0*DMODEL + col] = v0;
                *(float2*)&Cf[(size_t)r1*DMODEL + col] = v1;
            }
        }
    }
}

// ---------------- Flash attention (bf16x3, cp.async 2-stage K/V) ------------
// grid (SEQ/64, B*H), 128 threads (4 warps). Warp w owns query rows [w*16,+16).
// K/V smem: per stage {Kh,Kl,Vh,Vl}, each 64 rows x 128B, SW128 swizzle.
// P (softmax probs) hi/lo: padded layout AST=72 (warp-private rows).
#define ASTAGE 32768
#define AST 72
#define P_OFF 65536
#define KM_OFF (P_OFF + 2*64*AST*2)
#define ATTN_SMEM (KM_OFF + 2*64*4)

__global__ __launch_bounds__(128, 1) void attn_cp_kernel(
    const __nv_bfloat16* __restrict__ qhh, const __nv_bfloat16* __restrict__ qhl,
    const __nv_bfloat16* __restrict__ khh, const __nv_bfloat16* __restrict__ khl,
    const __nv_bfloat16* __restrict__ vhh, const __nv_bfloat16* __restrict__ vhl,
    __nv_bfloat16* __restrict__ obh, __nv_bfloat16* __restrict__ obl)
{
    extern __shared__ __align__(128) unsigned char smraw[];
    __nv_bfloat16* Psh = (__nv_bfloat16*)(smraw + P_OFF);
    __nv_bfloat16* Psl = Psh + 64*AST;
    float* kmf = (float*)(smraw + KM_OFF);

    int t = threadIdx.x, lane = t & 31, w = t >> 5;
    int g = lane >> 2, cq = (lane & 3) * 2;
    int qt = blockIdx.x, bh = blockIdx.y;
    int b = bh >> 4, h = bh & 15;
    int q0 = qt * 64;
    size_t bhoff = (size_t)bh * SEQ * HDIM;
    const __nv_bfloat16* qbh = qhh + bhoff + (size_t)q0 * HDIM;
    const __nv_bfloat16* qbl = qhl + bhoff + (size_t)q0 * HDIM;
    const unsigned char* mb = g_mask + b * SEQ;

    uint32_t sbse = (uint32_t)__cvta_generic_to_shared(smraw);
    const uint32_t PshB = sbse + P_OFF;
    const uint32_t PslB = PshB + 64*AST*2;
    uint32_t aoff = ((lane & 15) * AST + ((lane >> 4) << 3)) * 2;
    uint32_t x = (uint32_t)((lane & 7) << 4);

    int row = t >> 1, half = t & 1;
    uint32_t rxor = (uint32_t)((row & 7) << 4);
    const __nv_bfloat16* kvsrc[4] = {
        khh + bhoff + (size_t)row * HDIM + half * 32,
        khl + bhoff + (size_t)row * HDIM + half * 32,
        vhh + bhoff + (size_t)row * HDIM + half * 32,
        vhl + bhoff + (size_t)row * HDIM + half * 32 };

    auto issueKV = [&](int it2) {
        int st = it2 & 1;
        uint32_t base = sbse + st * ASTAGE + row * 128;
        size_t koff = (size_t)it2 * 64 * HDIM;
        #pragma unroll
        for (int rgn = 0; rgn < 4; ++rgn) {
            const __nv_bfloat16* src = kvsrc[rgn] + koff;
            uint32_t db = base + rgn * 8192;
            #pragma unroll
            for (int j = 0; j < 4; ++j) {
                uint32_t c = (uint32_t)(half * 64 + j * 16) ^ rxor;
                CP16(db + c, src + j * 8);
            }
        }
        if (t < 64) kmf[st*64 + t] = mb[it2*64 + t] ? 0.0f : NEG_INF;
    };

    issueKV(0); CP_COMMIT();

    // stage Q into P region, load persistent Q fragments (padded layout)
    {
        uint32_t sdst = (uint32_t)(row * AST * 2 + half * 64);
        const uint4* gqh = (const uint4*)(qbh + row * HDIM + half * 32);
        const uint4* gql = (const uint4*)(qbl + row * HDIM + half * 32);
        #pragma unroll
        for (int j = 0; j < 4; ++j) {
            *(uint4*)((char*)Psh + sdst + j*16) = gqh[j];
            *(uint4*)((char*)Psl + sdst + j*16) = gql[j];
        }
    }
    __syncthreads();
    uint32_t qfh[4][4], qfl[4][4];
    #pragma unroll
    for (int kt = 0; kt < 4; ++kt) {
        uint32_t base = (uint32_t)(w*16*AST + kt*16)*2 + aoff;
        ldm_x4(qfh[kt], PshB + base);
        ldm_x4(qfl[kt], PslB + base);
    }

    float oc[8][4] = {};
    float m0r = NEG_INF, m1r = NEG_INF, l0r = 0.f, l1r = 0.f;
    uint32_t krow = (uint32_t)(lane & 7);
    uint32_t kcol = (uint32_t)(((lane >> 3) & 1) << 4);
    uint32_t vrow = (uint32_t)(lane & 15);

    const int NT = SEQ / 64;   // 32
    for (int it = 0; it < NT; ++it) {
        if (it + 1 < NT) { issueKV(it + 1); CP_COMMIT(); CP_WAIT(1); }
        else { CP_WAIT(0); }
        __syncthreads();

        uint32_t stage = sbse + (uint32_t)(it & 1) * ASTAGE;
        const uint32_t KhB = stage, KlB = stage + 8192;
        const uint32_t VhB = stage + 16384, VlB = stage + 24576;
        const float* km = kmf + (it & 1) * 64;

        // S = Q K^T  (16 rows x 64 keys per warp)
        float sc[8][4] = {};
        #pragma unroll
        for (int nt = 0; nt < 8; ++nt) {
            uint32_t rbase = (uint32_t)(nt*8) + krow;
            #pragma unroll
            for (int kt = 0; kt < 4; ++kt) {
                uint32_t c = ((uint32_t)(kt*32) + kcol) ^ x;
                uint32_t b2h[2], b2l[2];
                ldm_x2(b2h, KhB + rbase*128 + c);
                ldm_x2(b2l, KlB + rbase*128 + c);
                mma16816(sc[nt], qfh[kt], b2h);
                mma16816(sc[nt], qfh[kt], b2l);
                mma16816(sc[nt], qfl[kt], b2h);
            }
        }

        // online softmax (rows g and g+8 of warp strip)
        float r0m = NEG_INF, r1m = NEG_INF;
        #pragma unroll
        for (int nt = 0; nt < 8; ++nt) {
            float a0 = km[nt*8 + cq], a1 = km[nt*8 + cq + 1];
            sc[nt][0] = sc[nt][0]*0.125f + a0;
            sc[nt][1] = sc[nt][1]*0.125f + a1;
            sc[nt][2] = sc[nt][2]*0.125f + a0;
            sc[nt][3] = sc[nt][3]*0.125f + a1;
            r0m = fmaxf(r0m, fmaxf(sc[nt][0], sc[nt][1]));
            r1m = fmaxf(r1m, fmaxf(sc[nt][2], sc[nt][3]));
        }
        r0m = fmaxf(r0m, __shfl_xor_sync(0xffffffffu, r0m, 1));
        r0m = fmaxf(r0m, __shfl_xor_sync(0xffffffffu, r0m, 2));
        r1m = fmaxf(r1m, __shfl_xor_sync(0xffffffffu, r1m, 1));
        r1m = fmaxf(r1m, __shfl_xor_sync(0xffffffffu, r1m, 2));
        float mn0 = fmaxf(m0r, r0m), mn1 = fmaxf(m1r, r1m);
        float ms0 = (mn0 == NEG_INF) ? 0.0f : mn0;
        float ms1 = (mn1 == NEG_INF) ? 0.0f : mn1;
        float al0 = __expf(m0r - ms0), al1 = __expf(m1r - ms1);
        m0r = mn0; m1r = mn1;

        float rs0 = 0.f, rs1 = 0.f;
        int pr0 = (w*16 + g) * AST, pr1 = (w*16 + g + 8) * AST;
        #pragma unroll
        for (int nt = 0; nt < 8; ++nt) {
            float p0 = __expf(sc[nt][0] - ms0), p1 = __expf(sc[nt][1] - ms0);
            float p2 = __expf(sc[nt][2] - ms1), p3 = __expf(sc[nt][3] - ms1);
            rs0 += p0 + p1; rs1 += p2 + p3;
            __nv_bfloat162 hv0, hv1, lv0, lv1;
            hv0.x = __float2bfloat16(p0); hv0.y = __float2bfloat16(p1);
            hv1.x = __float2bfloat16(p2); hv1.y = __float2bfloat16(p3);
            lv0.x = __float2bfloat16(p0 - __bfloat162float(hv0.x));
            lv0.y = __float2bfloat16(p1 - __bfloat162float(hv0.y));
            lv1.x = __float2bfloat16(p2 - __bfloat162float(hv1.x));
            lv1.y = __float2bfloat16(p3 - __bfloat162float(hv1.y));
            *(__nv_bfloat162*)(Psh + pr0 + nt*8 + cq) = hv0;
            *(__nv_bfloat162*)(Psh + pr1 + nt*8 + cq) = hv1;
            *(__nv_bfloat162*)(Psl + pr0 + nt*8 + cq) = lv0;
            *(__nv_bfloat162*)(Psl + pr1 + nt*8 + cq) = lv1;
        }
        rs0 += __shfl_xor_sync(0xffffffffu, rs0, 1);
        rs0 += __shfl_xor_sync(0xffffffffu, rs0, 2);
        rs1 += __shfl_xor_sync(0xffffffffu, rs1, 1);
        rs1 += __shfl_xor_sync(0xffffffffu, rs1, 2);
        l0r = l0r * al0 + rs0;
        l1r = l1r * al1 + rs1;
        #pragma unroll
        for (int nt = 0; nt < 8; ++nt) {
            oc[nt][0] *= al0; oc[nt][1] *= al0;
            oc[nt][2] *= al1; oc[nt][3] *= al1;
        }
        __syncwarp();   // P rows are warp-private

        // O += P V
        #pragma unroll
        for (int kt = 0; kt < 4; ++kt) {
            uint32_t pb = (uint32_t)(w*16*AST + kt*16)*2 + aoff;
            uint32_t pfh[4], pfl[4];
            ldm_x4(pfh, PshB + pb);
            ldm_x4(pfl, PslB + pb);
            uint32_t vr = ((uint32_t)(kt*16) + vrow) * 128;
            #pragma unroll
            for (int nt = 0; nt < 8; ++nt) {
                uint32_t c = ((uint32_t)(nt*16)) ^ x;
                uint32_t v2h[2], v2l[2];
                ldm_x2t(v2h, VhB + vr + c);
                ldm_x2t(v2l, VlB + vr + c);
                mma16816(oc[nt], pfh, v2h);
                mma16816(oc[nt], pfh, v2l);
                mma16816(oc[nt], pfl, v2h);
            }
        }
        __syncthreads();
    }

    // epilogue: normalize, zero masked query rows, write (b,s,d) as bf16 hi/lo
    int r0 = w*16 + g, r1 = r0 + 8;
    float inv0 = (mb[q0 + r0] && l0r > 0.f) ? 1.0f / l0r : 0.0f;
    float inv1 = (mb[q0 + r1] && l1r > 0.f) ? 1.0f / l1r : 0.0f;
    size_t base0 = ((size_t)b*SEQ + q0 + r0)*DMODEL + h*HDIM;
    size_t base1 = ((size_t)b*SEQ + q0 + r1)*DMODEL + h*HDIM;
    #pragma unroll
    for (int nt = 0; nt < 8; ++nt) {
        float v00 = oc[nt][0]*inv0, v01 = oc[nt][1]*inv0;
        float v10 = oc[nt][2]*inv1, v11 = oc[nt][3]*inv1;
        __nv_bfloat162 h0, l0, h1, l1;
        h0.x = __float2bfloat16(v00); h0.y = __float2bfloat16(v01);
        l0.x = __float2bfloat16(v00 - __bfloat162float(h0.x));
        l0.y = __float2bfloat16(v01 - __bfloat162float(h0.y));
        h1.x = __float2bfloat16(v10); h1.y = __float2bfloat16(v11);
        l1.x = __float2bfloat16(v10 - __bfloat162float(h1.x));
        l1.y = __float2bfloat16(v11 - __bfloat162float(h1.y));
        *(__nv_bfloat162*)(obh + base0 + nt*8 + cq) = h0;
        *(__nv_bfloat162*)(obl + base0 + nt*8 + cq) = l0;
        *(__nv_bfloat162*)(obh + base1 + nt*8 + cq) = h1;
        *(__nv_bfloat162*)(obl + base1 + nt*8 + cq) = l1;
    }
}

// ---------------- launch ----------------------------------------------------
extern "C" void kernel_launch(void* const* d_in, const int* in_sizes, int n_in,
                              void* d_out, int out_size) {
    const float* q    = (const float*)d_in[0];
    const unsigned char* mask = (const unsigned char*)d_in[1];
    const float* Wq   = (const float*)d_in[2];
    const float* bq   = (const float*)d_in[3];
    const float* Wk   = (const float*)d_in[4];
    const float* bk   = (const float*)d_in[5];
    const float* Wv   = (const float*)d_in[6];
    const float* bv   = (const float*)d_in[7];
    const float* Wo   = (const float*)d_in[8];
    const float* bo   = (const float*)d_in[9];
    float* out = (float*)d_out;

    __nv_bfloat16 *ah, *al, *wh, *wl, *qhh, *qhl, *khh, *khl, *vhh, *vhl, *oh, *ol;
    cudaGetSymbolAddress((void**)&ah,  g_ah);
    cudaGetSymbolAddress((void**)&al,  g_al);
    cudaGetSymbolAddress((void**)&wh,  g_wh);
    cudaGetSymbolAddress((void**)&wl,  g_wl);
    cudaGetSymbolAddress((void**)&qhh, g_qhh);
    cudaGetSymbolAddress((void**)&qhl, g_qhl);
    cudaGetSymbolAddress((void**)&khh, g_khh);
    cudaGetSymbolAddress((void**)&khl, g_khl);
    cudaGetSymbolAddress((void**)&vhh, g_vhh);
    cudaGetSymbolAddress((void**)&vhl, g_vhl);
    cudaGetSymbolAddress((void**)&oh,  g_oh);
    cudaGetSymbolAddress((void**)&ol,  g_ol);

    detect_mask_kernel<<<1, 256>>>(mask);
    convert_mask_kernel<<<(BATCH*SEQ + 255) / 256, 256>>>(mask);

    split_kernel<<<NELEM / 1024, 256>>>(q, ah, al, NELEM);
    split_w_kernel<<<dim3(1024, 1, 4), 256>>>(Wq, Wk, Wv, Wo, wh, wl);

    const int gemm_smem = 3 * GSTAGE;   // 98304 B
    static bool attr_done = false;
    if (!attr_done) {
        cudaFuncSetAttribute(gemm_cp_kernel<true>,
                             cudaFuncAttributeMaxDynamicSharedMemorySize, gemm_smem);
        cudaFuncSetAttribute(gemm_cp_kernel<false>,
                             cudaFuncAttributeMaxDynamicSharedMemorySize, gemm_smem);
        cudaFuncSetAttribute(attn_cp_kernel,
                             cudaFuncAttributeMaxDynamicSharedMemorySize, ATTN_SMEM);
        attr_done = true;
    }

    // fused QKV projections
    gemm_cp_kernel<true><<<dim3(8, 64, 3), 256, gemm_smem>>>(
        ah, al, wh, wl, 0, bq, bk, bv,
        qhh, qhl, khh, khl, vhh, vhl, nullptr);

    attn_cp_kernel<<<dim3(SEQ / 64, BATCH * NHEAD), 128, ATTN_SMEM>>>(
        qhh, qhl, khh, khl, vhh, vhl, oh, ol);

    // output projection -> fp32 out
    gemm_cp_kernel<false><<<dim3(8, 64, 1), 256, gemm_smem>>>(
        oh, ol, wh, wl, 3, bo, bo, bo,
        nullptr, nullptr, nullptr, nullptr, nullptr, nullptr, out);
}

// round 6
// speedup vs baseline: 1.2019x; 1.0495x over previous
#include <cuda_runtime.h>
#include <cuda_bf16.h>
#include <cstdint>

// Problem constants
#define BATCH 4
#define SEQ   2048
#define DMODEL 1024
#define NHEAD 16
#define HDIM  64
#define MROWS (BATCH*SEQ)         // 8192

#define NEG_INF __int_as_float(0xff800000)

// ---------------- scratch (device globals; no allocation allowed) ----------
#define NELEM (8192*1024)
__device__ __nv_bfloat16 g_ah[NELEM],  g_al[NELEM];            // input q hi/lo
__device__ __nv_bfloat16 g_wh[4*1024*1024], g_wl[4*1024*1024]; // Wq,Wk,Wv,Wo hi/lo
__device__ __nv_bfloat16 g_qhh[NELEM], g_qhl[NELEM];           // Q heads (b,h,s,hd)
__device__ __nv_bfloat16 g_khh[NELEM], g_khl[NELEM];
__device__ __nv_bfloat16 g_vhh[NELEM], g_vhl[NELEM];
__device__ __nv_bfloat16 g_oh[NELEM],  g_ol[NELEM];            // attn out (b,s,d)
__device__ unsigned char g_mask[BATCH*SEQ];
__device__ int g_mode;

// ---------------- mask dtype detection + canonicalization ------------------
__global__ void detect_mask_kernel(const unsigned char* __restrict__ p) {
    __shared__ int s1, s3;
    if (threadIdx.x == 0) { s1 = 0; s3 = 0; }
    __syncthreads();
    int l1 = 0, l3 = 0;
    for (int i = threadIdx.x; i < BATCH*SEQ; i += blockDim.x) {
        unsigned char v = p[i];
        int m = i & 3;
        if (m == 1 && v) l1 = 1;
        if (m == 3 && v) l3 = 1;
    }
    if (l1) atomicOr(&s1, 1);
    if (l3) atomicOr(&s3, 1);
    __syncthreads();
    if (threadIdx.x == 0) g_mode = s1 ? 0 : (s3 ? 1 : 2);  // 0=u8, 1=f32, 2=i32
}

__global__ void convert_mask_kernel(const unsigned char* __restrict__ p) {
    int i = blockIdx.x * blockDim.x + threadIdx.x;
    if (i >= BATCH*SEQ) return;
    int mode = g_mode;
    unsigned char r;
    if (mode == 0)      r = (p[i] != 0);
    else if (mode == 1) r = (((const float*)p)[i] != 0.0f);
    else                r = (((const int*)p)[i] != 0);
    g_mask[i] = r;
}

// ---------------- fp32 -> bf16 hi/lo split kernels --------------------------
__device__ __forceinline__ void split4(float4 v, __nv_bfloat16* h, __nv_bfloat16* l) {
    float f[4] = {v.x, v.y, v.z, v.w};
    #pragma unroll
    for (int p = 0; p < 2; ++p) {
        __nv_bfloat162 hp, lp;
        hp.x = __float2bfloat16(f[2*p]);
        hp.y = __float2bfloat16(f[2*p+1]);
        lp.x = __float2bfloat16(f[2*p]   - __bfloat162float(hp.x));
        lp.y = __float2bfloat16(f[2*p+1] - __bfloat162float(hp.y));
        *(__nv_bfloat162*)(h + 2*p) = hp;
        *(__nv_bfloat162*)(l + 2*p) = lp;
    }
}

__global__ void split_kernel(const float* __restrict__ src,
                             __nv_bfloat16* __restrict__ hi,
                             __nv_bfloat16* __restrict__ lo, int n) {
    int i = (blockIdx.x * blockDim.x + threadIdx.x) * 4;
    if (i >= n) return;
    split4(*(const float4*)(src + i), hi + i, lo + i);
}

__global__ void split_w_kernel(const float* __restrict__ w0, const float* __restrict__ w1,
                               const float* __restrict__ w2, const float* __restrict__ w3,
                               __nv_bfloat16* __restrict__ hi, __nv_bfloat16* __restrict__ lo) {
    int z = blockIdx.z;
    const float* src = (z==0)?w0:(z==1)?w1:(z==2)?w2:w3;
    size_t off = (size_t)z * 1024 * 1024;
    int i = (blockIdx.x * blockDim.x + threadIdx.x) * 4;
    split4(*(const float4*)(src + i), hi + off + i, lo + off + i);
}

// ---------------- mma / ldmatrix / cp.async primitives ----------------------
__device__ __forceinline__ void mma16816(float* c, const uint32_t* a, const uint32_t* b) {
    asm volatile(
        "mma.sync.aligned.m16n8k16.row.col.f32.bf16.bf16.f32 "
        "{%0,%1,%2,%3}, {%4,%5,%6,%7}, {%8,%9}, {%0,%1,%2,%3};"
        : "+f"(c[0]), "+f"(c[1]), "+f"(c[2]), "+f"(c[3])
        : "r"(a[0]), "r"(a[1]), "r"(a[2]), "r"(a[3]), "r"(b[0]), "r"(b[1]));
}
__device__ __forceinline__ void ldm_x4(uint32_t* r, uint32_t addr) {
    asm volatile("ldmatrix.sync.aligned.m8n8.x4.shared.b16 {%0,%1,%2,%3}, [%4];"
                 : "=r"(r[0]), "=r"(r[1]), "=r"(r[2]), "=r"(r[3]) : "r"(addr));
}
__device__ __forceinline__ void ldm_x2(uint32_t* r, uint32_t addr) {
    asm volatile("ldmatrix.sync.aligned.m8n8.x2.shared.b16 {%0,%1}, [%2];"
                 : "=r"(r[0]), "=r"(r[1]) : "r"(addr));
}
__device__ __forceinline__ void ldm_x2t(uint32_t* r, uint32_t addr) {
    asm volatile("ldmatrix.sync.aligned.m8n8.x2.trans.shared.b16 {%0,%1}, [%2];"
                 : "=r"(r[0]), "=r"(r[1]) : "r"(addr));
}
#define CP16(dst, src) \
    asm volatile("cp.async.cg.shared.global [%0], [%1], 16;" :: "r"(dst), "l"(src))
#define CP_COMMIT() asm volatile("cp.async.commit_group;" ::: "memory")
#define CP_WAIT(n)  asm volatile("cp.async.wait_group %0;" :: "n"(n) : "memory")

// ---------------- GEMM: C = A @ W^T + bias (bf16x3, cp.async 3-stage) -------
// A hi/lo, W hi/lo: bf16 [.,1024] row-major. BM=BN=128, BK=32.
// smem stage: region A = 128 rows x 128B [hi 64B | lo 64B], region B same.
// SW128 swizzle: chunk bits [6:4] ^= row&7.  8 warps (2x4), warp tile 64x32.
// One __syncthreads per iteration (reuse distance 3; sync precedes issue).
#define GSTAGE 32768
#define NIT 32

template <bool SPLIT>
__global__ __launch_bounds__(256, 1) void gemm_cp_kernel(
    const __nv_bfloat16* __restrict__ Ahg, const __nv_bfloat16* __restrict__ Alg,
    const __nv_bfloat16* __restrict__ Whb, const __nv_bfloat16* __restrict__ Wlb, int woff,
    const float* b0, const float* b1, const float* b2,
    __nv_bfloat16* C0h, __nv_bfloat16* C0l,
    __nv_bfloat16* C1h, __nv_bfloat16* C1l,
    __nv_bfloat16* C2h, __nv_bfloat16* C2l,
    float* Cf)
{
    int z = blockIdx.z;
    const __nv_bfloat16* Wh = Whb + (size_t)(woff + z) * 1024 * 1024;
    const __nv_bfloat16* Wl = Wlb + (size_t)(woff + z) * 1024 * 1024;
    const float* bias = (z == 0) ? b0 : (z == 1) ? b1 : b2;
    __nv_bfloat16* Ch = (z == 0) ? C0h : (z == 1) ? C1h : C2h;
    __nv_bfloat16* Cl = (z == 0) ? C0l : (z == 1) ? C1l : C2l;

    extern __shared__ __align__(128) unsigned char smraw[];
    uint32_t sb = (uint32_t)__cvta_generic_to_shared(smraw);

    int t = threadIdx.x, lane = t & 31, warp = t >> 5;
    int wm = warp >> 2, wn = warp & 3;
    int m0 = blockIdx.y * 128, n0 = blockIdx.x * 128;

    int row = t >> 1, half = t & 1;
    const __nv_bfloat16* srcA = (half ? Alg : Ahg) + (size_t)(m0 + row) * 1024;
    const __nv_bfloat16* srcB = (half ? Wl : Wh)  + (size_t)(n0 + row) * 1024;
    uint32_t rxor = (uint32_t)((row & 7) << 4);
    uint32_t dA = sb + row * 128;

    auto issue = [&](int ch) {
        uint32_t base = dA + (uint32_t)(ch % 3) * GSTAGE;
        const __nv_bfloat16* sa = srcA + ch * 32;
        const __nv_bfloat16* sbp = srcB + ch * 32;
        #pragma unroll
        for (int j = 0; j < 4; ++j) {
            uint32_t c = (uint32_t)(half * 64 + j * 16) ^ rxor;
            CP16(base + c,         sa  + j * 8);
            CP16(base + 16384 + c, sbp + j * 8);
        }
    };

    float c[4][4][4] = {};
    uint32_t x = (uint32_t)((lane & 7) << 4);
    uint32_t arow = (uint32_t)(wm * 64 + (lane & 15));
    uint32_t acol = (uint32_t)((lane >> 4) << 4);
    uint32_t brow = (uint32_t)(wn * 32 + (lane & 7));
    uint32_t bcol = (uint32_t)(((lane >> 3) & 1) << 4);

    issue(0); CP_COMMIT();
    issue(1); CP_COMMIT();

    for (int it = 0; it < NIT; ++it) {
        if (it + 1 < NIT) { CP_WAIT(1); } else { CP_WAIT(0); }
        __syncthreads();
        if (it + 2 < NIT) { issue(it + 2); CP_COMMIT(); }

        uint32_t Abase = sb + (uint32_t)(it % 3) * GSTAGE;
        uint32_t Bbase = Abase + 16384;
        #pragma unroll
        for (int ks = 0; ks < 2; ++ks) {
            uint32_t ch = (uint32_t)(ks * 32) + acol;
            uint32_t afh[4][4], afl[4][4];
            #pragma unroll
            for (int mi = 0; mi < 4; ++mi) {
                uint32_t ra = Abase + (arow + mi * 16) * 128;
                ldm_x4(afh[mi], ra + (ch ^ x));
                ldm_x4(afl[mi], ra + ((ch + 64) ^ x));
            }
            uint32_t cb = (uint32_t)(ks * 32) + bcol;
            uint32_t bfh[4][2], bfl[4][2];
            #pragma unroll
            for (int ni = 0; ni < 4; ++ni) {
                uint32_t rb = Bbase + (brow + ni * 8) * 128;
                ldm_x2(bfh[ni], rb + (cb ^ x));
                ldm_x2(bfl[ni], rb + ((cb + 64) ^ x));
            }
            #pragma unroll
            for (int mi = 0; mi < 4; ++mi)
                #pragma unroll
                for (int ni = 0; ni < 4; ++ni) {
                    mma16816(c[mi][ni], afh[mi], bfh[ni]);
                    mma16816(c[mi][ni], afh[mi], bfl[ni]);
                    mma16816(c[mi][ni], afl[mi], bfh[ni]);
                }
        }
    }

    // epilogue
    int g = lane >> 2, cq = (lane & 3) * 2;
    #pragma unroll
    for (int mi = 0; mi < 4; ++mi) {
        int r0 = m0 + wm*64 + mi*16 + g;
        int r1 = r0 + 8;
        #pragma unroll
        for (int ni = 0; ni < 4; ++ni) {
            int col = n0 + wn*32 + ni*8 + cq;
            float b0v = __ldg(bias + col), b1v = __ldg(bias + col + 1);
            float v00 = c[mi][ni][0] + b0v, v01 = c[mi][ni][1] + b1v;
            float v10 = c[mi][ni][2] + b0v, v11 = c[mi][ni][3] + b1v;
            if (SPLIT) {
                int hh = col >> 6, hd = col & 63;
                int bi0 = r0 >> 11, s0 = r0 & 2047;
                int bi1 = r1 >> 11, s1 = r1 & 2047;
                size_t i0 = ((((size_t)bi0*NHEAD + hh)*SEQ) + s0)*HDIM + hd;
                size_t i1 = ((((size_t)bi1*NHEAD + hh)*SEQ) + s1)*HDIM + hd;
                __nv_bfloat162 h2, l2;
                h2.x = __float2bfloat16(v00); h2.y = __float2bfloat16(v01);
                l2.x = __float2bfloat16(v00 - __bfloat162float(h2.x));
                l2.y = __float2bfloat16(v01 - __bfloat162float(h2.y));
                *(__nv_bfloat162*)(Ch + i0) = h2;
                *(__nv_bfloat162*)(Cl + i0) = l2;
                h2.x = __float2bfloat16(v10); h2.y = __float2bfloat16(v11);
                l2.x = __float2bfloat16(v10 - __bfloat162float(h2.x));
                l2.y = __float2bfloat16(v11 - __bfloat162float(h2.y));
                *(__nv_bfloat162*)(Ch + i1) = h2;
                *(__nv_bfloat162*)(Cl + i1) = l2;
            } else {
                float2 v0 = {v00, v01}, v1 = {v10, v11};
                *(float2*)&Cf[(size_t)r0*DMODEL + col] = v0;
                *(float2*)&Cf[(size_t)r1*DMODEL + col] = v1;
            }
        }
    }
}

// ---------------- Flash attention (bf16x3, 3-stage cp.async, P-in-regs) -----
// grid (SEQ/64, B*H), 128 threads (4 warps). Warp w owns query rows [w*16,+16).
// K/V smem per stage: {Kh,Kl,Vh,Vl} x 64 rows x 128B, SW128-style swizzle.
// P never touches smem: QK^T C-fragments are repacked into PV A-fragments.
#define ASTG 32768
#define KM_OFF (3*ASTG)
#define ATTN_SMEM (KM_OFF + 3*64*4)

__global__ __launch_bounds__(128, 1) void attn_cp_kernel(
    const __nv_bfloat16* __restrict__ qhh, const __nv_bfloat16* __restrict__ qhl,
    const __nv_bfloat16* __restrict__ khh, const __nv_bfloat16* __restrict__ khl,
    const __nv_bfloat16* __restrict__ vhh, const __nv_bfloat16* __restrict__ vhl,
    __nv_bfloat16* __restrict__ obh, __nv_bfloat16* __restrict__ obl)
{
    extern __shared__ __align__(128) unsigned char smraw[];
    float* kmf = (float*)(smraw + KM_OFF);

    int t = threadIdx.x, lane = t & 31, w = t >> 5;
    int g = lane >> 2, cq = (lane & 3) * 2;
    int qt = blockIdx.x, bh = blockIdx.y;
    int b = bh >> 4, h = bh & 15;
    int q0 = qt * 64;
    size_t bhoff = (size_t)bh * SEQ * HDIM;
    const __nv_bfloat16* qbh = qhh + bhoff + (size_t)q0 * HDIM;
    const __nv_bfloat16* qbl = qhl + bhoff + (size_t)q0 * HDIM;
    const unsigned char* mb = g_mask + b * SEQ;

    uint32_t sbse = (uint32_t)__cvta_generic_to_shared(smraw);
    uint32_t x = (uint32_t)((lane & 7) << 4);

    int row = t >> 1, half = t & 1;
    uint32_t rxor = (uint32_t)((row & 7) << 4);
    const __nv_bfloat16* kvsrc[4] = {
        khh + bhoff + (size_t)row * HDIM + half * 32,
        khl + bhoff + (size_t)row * HDIM + half * 32,
        vhh + bhoff + (size_t)row * HDIM + half * 32,
        vhl + bhoff + (size_t)row * HDIM + half * 32 };

    auto issueKV = [&](int it2) {
        int st = it2 % 3;
        uint32_t base = sbse + st * ASTG + row * 128;
        size_t koff = (size_t)it2 * 64 * HDIM;
        #pragma unroll
        for (int rgn = 0; rgn < 4; ++rgn) {
            const __nv_bfloat16* src = kvsrc[rgn] + koff;
            uint32_t db = base + rgn * 8192;
            #pragma unroll
            for (int j = 0; j < 4; ++j) {
                uint32_t c = (uint32_t)(half * 64 + j * 16) ^ rxor;
                CP16(db + c, src + j * 8);
            }
        }
        if (t < 64) kmf[st*64 + t] = mb[it2*64 + t] ? 0.0f : NEG_INF;
    };

    issueKV(0); CP_COMMIT();
    issueKV(1); CP_COMMIT();

    // stage Q into stage-2 buffer (Qh at +0, Ql at +8192); overwritten at it=0
    // only AFTER the first loop sync, by which point Q frags are in registers.
    {
        uint32_t qdst = sbse + 2*ASTG + row * 128;
        const uint4* gqh = (const uint4*)(qbh + row * HDIM + half * 32);
        const uint4* gql = (const uint4*)(qbl + row * HDIM + half * 32);
        #pragma unroll
        for (int j = 0; j < 4; ++j) {
            uint32_t c = (uint32_t)(half * 64 + j * 16) ^ rxor;
            asm volatile("st.shared.v4.b32 [%0], {%1,%2,%3,%4};" ::
                "r"(qdst + c), "r"(gqh[j].x), "r"(gqh[j].y), "r"(gqh[j].z), "r"(gqh[j].w));
            asm volatile("st.shared.v4.b32 [%0], {%1,%2,%3,%4};" ::
                "r"(qdst + 8192 + c), "r"(gql[j].x), "r"(gql[j].y), "r"(gql[j].z), "r"(gql[j].w));
        }
    }
    __syncthreads();
    uint32_t qfh[4][4], qfl[4][4];
    {
        uint32_t qrow = (uint32_t)(w*16 + (lane & 15));
        uint32_t qc = (uint32_t)((lane >> 4) << 4);
        #pragma unroll
        for (int kt = 0; kt < 4; ++kt) {
            uint32_t c = ((uint32_t)(kt*32) + qc) ^ x;
            uint32_t addr = sbse + 2*ASTG + qrow * 128 + c;
            ldm_x4(qfh[kt], addr);
            ldm_x4(qfl[kt], addr + 8192);
        }
    }

    float oc[8][4] = {};
    float m0r = NEG_INF, m1r = NEG_INF, l0r = 0.f, l1r = 0.f;
    uint32_t krow = (uint32_t)(lane & 7);
    uint32_t kcol = (uint32_t)(((lane >> 3) & 1) << 4);
    uint32_t vrow = (uint32_t)(lane & 15);

    const int NT = SEQ / 64;   // 32
    for (int it = 0; it < NT; ++it) {
        if (it + 1 < NT) { CP_WAIT(1); } else { CP_WAIT(0); }
        __syncthreads();   // stage it%3 visible; all warps done with it-1
        if (it + 2 < NT) { issueKV(it + 2); CP_COMMIT(); }

        uint32_t stage = sbse + (uint32_t)(it % 3) * ASTG;
        const uint32_t KhB = stage, KlB = stage + 8192;
        const uint32_t VhB = stage + 16384, VlB = stage + 24576;
        const float* km = kmf + (it % 3) * 64;

        // S = Q K^T  (16 rows x 64 keys per warp)
        float sc[8][4] = {};
        #pragma unroll
        for (int nt = 0; nt < 8; ++nt) {
            uint32_t rbase = ((uint32_t)(nt*8) + krow) * 128;
            #pragma unroll
            for (int kt = 0; kt < 4; ++kt) {
                uint32_t c = ((uint32_t)(kt*32) + kcol) ^ x;
                uint32_t b2h[2], b2l[2];
                ldm_x2(b2h, KhB + rbase + c);
                ldm_x2(b2l, KlB + rbase + c);
                mma16816(sc[nt], qfh[kt], b2h);
                mma16816(sc[nt], qfh[kt], b2l);
                mma16816(sc[nt], qfl[kt], b2h);
            }
        }

        // online softmax (rows g and g+8 of warp strip)
        float r0m = NEG_INF, r1m = NEG_INF;
        #pragma unroll
        for (int nt = 0; nt < 8; ++nt) {
            float a0 = km[nt*8 + cq], a1 = km[nt*8 + cq + 1];
            sc[nt][0] = sc[nt][0]*0.125f + a0;
            sc[nt][1] = sc[nt][1]*0.125f + a1;
            sc[nt][2] = sc[nt][2]*0.125f + a0;
            sc[nt][3] = sc[nt][3]*0.125f + a1;
            r0m = fmaxf(r0m, fmaxf(sc[nt][0], sc[nt][1]));
            r1m = fmaxf(r1m, fmaxf(sc[nt][2], sc[nt][3]));
        }
        r0m = fmaxf(r0m, __shfl_xor_sync(0xffffffffu, r0m, 1));
        r0m = fmaxf(r0m, __shfl_xor_sync(0xffffffffu, r0m, 2));
        r1m = fmaxf(r1m, __shfl_xor_sync(0xffffffffu, r1m, 1));
        r1m = fmaxf(r1m, __shfl_xor_sync(0xffffffffu, r1m, 2));
        float mn0 = fmaxf(m0r, r0m), mn1 = fmaxf(m1r, r1m);
        float ms0 = (mn0 == NEG_INF) ? 0.0f : mn0;
        float ms1 = (mn1 == NEG_INF) ? 0.0f : mn1;
        float al0 = __expf(m0r - ms0), al1 = __expf(m1r - ms1);
        m0r = mn0; m1r = mn1;

        // exp + pack P directly into PV A-fragment registers:
        // A-frag for key chunk kt: {ph[2kt], ph2[2kt], ph[2kt+1], ph2[2kt+1]}
        // (C layout of QK mma == A layout of PV mma, rows g/g+8, k=2t,2t+1)
        uint32_t ph[8], ph2[8], pl[8], pl2[8];
        float rs0 = 0.f, rs1 = 0.f;
        #pragma unroll
        for (int nt = 0; nt < 8; ++nt) {
            float p0 = __expf(sc[nt][0] - ms0), p1 = __expf(sc[nt][1] - ms0);
            float p2 = __expf(sc[nt][2] - ms1), p3 = __expf(sc[nt][3] - ms1);
            rs0 += p0 + p1; rs1 += p2 + p3;
            __nv_bfloat162 hv0, hv1, lv0, lv1;
            hv0.x = __float2bfloat16(p0); hv0.y = __float2bfloat16(p1);
            hv1.x = __float2bfloat16(p2); hv1.y = __float2bfloat16(p3);
            lv0.x = __float2bfloat16(p0 - __bfloat162float(hv0.x));
            lv0.y = __float2bfloat16(p1 - __bfloat162float(hv0.y));
            lv1.x = __float2bfloat16(p2 - __bfloat162float(hv1.x));
            lv1.y = __float2bfloat16(p3 - __bfloat162float(hv1.y));
            ph[nt]  = *(uint32_t*)&hv0;
            ph2[nt] = *(uint32_t*)&hv1;
            pl[nt]  = *(uint32_t*)&lv0;
            pl2[nt] = *(uint32_t*)&lv1;
        }
        rs0 += __shfl_xor_sync(0xffffffffu, rs0, 1);
        rs0 += __shfl_xor_sync(0xffffffffu, rs0, 2);
        rs1 += __shfl_xor_sync(0xffffffffu, rs1, 1);
        rs1 += __shfl_xor_sync(0xffffffffu, rs1, 2);
        l0r = l0r * al0 + rs0;
        l1r = l1r * al1 + rs1;
        #pragma unroll
        for (int nt = 0; nt < 8; ++nt) {
            oc[nt][0] *= al0; oc[nt][1] *= al0;
            oc[nt][2] *= al1; oc[nt][3] *= al1;
        }

        // O += P V  (P fragments straight from registers)
        #pragma unroll
        for (int kt = 0; kt < 4; ++kt) {
            uint32_t pa[4]  = {ph[2*kt],  ph2[2*kt],  ph[2*kt+1],  ph2[2*kt+1]};
            uint32_t pla[4] = {pl[2*kt],  pl2[2*kt],  pl[2*kt+1],  pl2[2*kt+1]};
            uint32_t vr = ((uint32_t)(kt*16) + vrow) * 128;
            #pragma unroll
            for (int nt = 0; nt < 8; ++nt) {
                uint32_t c = ((uint32_t)(nt*16)) ^ x;
                uint32_t v2h[2], v2l[2];
                ldm_x2t(v2h, VhB + vr + c);
                ldm_x2t(v2l, VlB + vr + c);
                mma16816(oc[nt], pa,  v2h);
                mma16816(oc[nt], pa,  v2l);
                mma16816(oc[nt], pla, v2h);
            }
        }
    }

    // epilogue: normalize, zero masked query rows, write (b,s,d) as bf16 hi/lo
    int r0 = w*16 + g, r1 = r0 + 8;
    float inv0 = (mb[q0 + r0] && l0r > 0.f) ? 1.0f / l0r : 0.0f;
    float inv1 = (mb[q0 + r1] && l1r > 0.f) ? 1.0f / l1r : 0.0f;
    size_t base0 = ((size_t)b*SEQ + q0 + r0)*DMODEL + h*HDIM;
    size_t base1 = ((size_t)b*SEQ + q0 + r1)*DMODEL + h*HDIM;
    #pragma unroll
    for (int nt = 0; nt < 8; ++nt) {
        float v00 = oc[nt][0]*inv0, v01 = oc[nt][1]*inv0;
        float v10 = oc[nt][2]*inv1, v11 = oc[nt][3]*inv1;
        __nv_bfloat162 h0, l0, h1, l1;
        h0.x = __float2bfloat16(v00); h0.y = __float2bfloat16(v01);
        l0.x = __float2bfloat16(v00 - __bfloat162float(h0.x));
        l0.y = __float2bfloat16(v01 - __bfloat162float(h0.y));
        h1.x = __float2bfloat16(v10); h1.y = __float2bfloat16(v11);
        l1.x = __float2bfloat16(v10 - __bfloat162float(h1.x));
        l1.y = __float2bfloat16(v11 - __bfloat162float(h1.y));
        *(__nv_bfloat162*)(obh + base0 + nt*8 + cq) = h0;
        *(__nv_bfloat162*)(obl + base0 + nt*8 + cq) = l0;
        *(__nv_bfloat162*)(obh + base1 + nt*8 + cq) = h1;
        *(__nv_bfloat162*)(obl + base1 + nt*8 + cq) = l1;
    }
}

// ---------------- launch ----------------------------------------------------
extern "C" void kernel_launch(void* const* d_in, const int* in_sizes, int n_in,
                              void* d_out, int out_size) {
    const float* q    = (const float*)d_in[0];
    const unsigned char* mask = (const unsigned char*)d_in[1];
    const float* Wq   = (const float*)d_in[2];
    const float* bq   = (const float*)d_in[3];
    const float* Wk   = (const float*)d_in[4];
    const float* bk   = (const float*)d_in[5];
    const float* Wv   = (const float*)d_in[6];
    const float* bv   = (const float*)d_in[7];
    const float* Wo   = (const float*)d_in[8];
    const float* bo   = (const float*)d_in[9];
    float* out = (float*)d_out;

    __nv_bfloat16 *ah, *al, *wh, *wl, *qhh, *qhl, *khh, *khl, *vhh, *vhl, *oh, *ol;
    cudaGetSymbolAddress((void**)&ah,  g_ah);
    cudaGetSymbolAddress((void**)&al,  g_al);
    cudaGetSymbolAddress((void**)&wh,  g_wh);
    cudaGetSymbolAddress((void**)&wl,  g_wl);
    cudaGetSymbolAddress((void**)&qhh, g_qhh);
    cudaGetSymbolAddress((void**)&qhl, g_qhl);
    cudaGetSymbolAddress((void**)&khh, g_khh);
    cudaGetSymbolAddress((void**)&khl, g_khl);
    cudaGetSymbolAddress((void**)&vhh, g_vhh);
    cudaGetSymbolAddress((void**)&vhl, g_vhl);
    cudaGetSymbolAddress((void**)&oh,  g_oh);
    cudaGetSymbolAddress((void**)&ol,  g_ol);

    detect_mask_kernel<<<1, 256>>>(mask);
    convert_mask_kernel<<<(BATCH*SEQ + 255) / 256, 256>>>(mask);

    split_kernel<<<NELEM / 1024, 256>>>(q, ah, al, NELEM);
    split_w_kernel<<<dim3(1024, 1, 4), 256>>>(Wq, Wk, Wv, Wo, wh, wl);

    const int gemm_smem = 3 * GSTAGE;   // 98304 B
    static bool attr_done = false;
    if (!attr_done) {
        cudaFuncSetAttribute(gemm_cp_kernel<true>,
                             cudaFuncAttributeMaxDynamicSharedMemorySize, gemm_smem);
        cudaFuncSetAttribute(gemm_cp_kernel<false>,
                             cudaFuncAttributeMaxDynamicSharedMemorySize, gemm_smem);
        cudaFuncSetAttribute(attn_cp_kernel,
                             cudaFuncAttributeMaxDynamicSharedMemorySize, ATTN_SMEM);
        attr_done = true;
    }

    // fused QKV projections
    gemm_cp_kernel<true><<<dim3(8, 64, 3), 256, gemm_smem>>>(
        ah, al, wh, wl, 0, bq, bk, bv,
        qhh, qhl, khh, khl, vhh, vhl, nullptr);

    attn_cp_kernel<<<dim3(SEQ / 64, BATCH * NHEAD), 128, ATTN_SMEM>>>(
        qhh, qhl, khh, khl, vhh, vhl, oh, ol);

    // output projection -> fp32 out
    gemm_cp_kernel<false><<<dim3(8, 64, 1), 256, gemm_smem>>>(
        oh, ol, wh, wl, 3, bo, bo, bo,
        nullptr, nullptr, nullptr, nullptr, nullptr, nullptr, out);
}